// round 13
// baseline (speedup 1.0000x reference)
#include <cuda_runtime.h>
#include <cstdint>

#define BATCH   32
#define NPRED   8400
#define NCLS    80
#define ROWF    85
#define KPRE    512
#define MAXOUT  100
#define RPB     120         // rows per k_score block: 120*85*4 = 40800 B smem
#define CONF_TH 0.25f
#define IOU_TH  0.45f
#define CLS_OFF 4096.0f
#define FULLM   0xFFFFFFFFu

// Scratch (no allocations allowed -> device globals)
__device__ unsigned long long g_keys[BATCH * NPRED];
__device__ float              g_rows[(size_t)BATCH * NPRED * 8]; // x1,y1,x2,y2,obj,conf,cls,pad

// ---------------------------------------------------------------------------
// K1: streaming pass. Block stages 120 rows into smem with coalesced LDG.128,
// then THREAD-per-row argmax (conflict-free: row stride 85 words, gcd(85,32)=1)
// -> ~11 warp-instr/row instead of ~40 (no shuffles). Emits the sort key
// (score_bits<<32 | ~n, unique) and the full 8-float det record.
// ---------------------------------------------------------------------------
__global__ void __launch_bounds__(128) k_score(const float* __restrict__ pred) {
    __shared__ float srow[RPB * ROWF];     // 40800 B
    int tid = threadIdx.x;                 // 128
    int b = blockIdx.y;
    int row0 = blockIdx.x * RPB;

    // base element index multiple of 4: RPB*ROWF = 10200, NPRED*ROWF = 714000
    const float4* src = (const float4*)(pred + ((size_t)b * NPRED + row0) * ROWF);
    float4* dst4 = (float4*)srow;
    for (int i = tid; i < RPB * ROWF / 4; i += 128) dst4[i] = src[i];
    __syncthreads();

    if (tid < RPB) {
        const float* row = srow + tid * ROWF;
        // first-occurrence argmax over 80 classes (strict >)
        float bv = row[5]; int bi = 0;
#pragma unroll 8
        for (int c = 1; c < NCLS; c++) {
            float v = row[5 + c];
            if (v > bv) { bv = v; bi = c; }
        }
        float cx = row[0], cy = row[1], w = row[2], h = row[3], obj = row[4];
        float score = obj * bv;                   // >= 0
        unsigned sb = __float_as_uint(score);     // positive-float bit order == int order
        int n = row0 + tid;
        g_keys[(size_t)b * NPRED + n] =
            ((unsigned long long)sb << 32) | (unsigned)(~(unsigned)n);
        float x1 = cx - 0.5f * w, y1 = cy - 0.5f * h;
        float x2 = cx + 0.5f * w, y2 = cy + 0.5f * h;
        float4* rec = (float4*)(g_rows + ((size_t)b * NPRED + n) * 8);
        rec[0] = make_float4(x1, y1, x2, y2);
        rec[1] = make_float4(obj, bv, (float)bi, 0.f);
    }
}

// ---------------------------------------------------------------------------
// K2 (fused): per-batch conf + exact top-512 radix select + bitonic sort +
// greedy NMS + emit. One 512-thread block per batch. After the sort, the box
// arrays alias the dead s_keys region (topsm at offset NPRED stays intact).
// ---------------------------------------------------------------------------
__global__ void k_selnms(float* __restrict__ out, int out_size) {
    extern __shared__ unsigned long long s_keys[];   // NPRED + KPRE entries
    unsigned long long* topsm = s_keys + NPRED;

    __shared__ unsigned int        hist[256];
    __shared__ unsigned int        wmax[16];
    __shared__ unsigned int        sh_confb;
    __shared__ unsigned long long  sh_prefix;
    __shared__ unsigned long long  sh_pivot;
    __shared__ int                 sh_remaining;
    __shared__ unsigned int        cnt;
    __shared__ unsigned long long  cand[256];
    __shared__ unsigned int        ccnt;
    __shared__ unsigned            salive[16];
    __shared__ int                 skept[MAXOUT];
    __shared__ int                 s_i;

    int b = blockIdx.x;
    int tid = threadIdx.x;                 // 512
    int warp = tid >> 5, lane = tid & 31;  // 16 warps
    const int NITER = (NPRED + 511) / 512; // uniform trip count (17)

    // ---- load keys + running max of score field ----
    unsigned mymax = 0u;
    for (int i = tid; i < NPRED; i += 512) {
        unsigned long long k = g_keys[(size_t)b * NPRED + i];
        s_keys[i] = k;
        unsigned sb = (unsigned)(k >> 32);
        mymax = mymax > sb ? mymax : sb;
    }
#pragma unroll
    for (int off = 16; off; off >>= 1) {
        unsigned v = __shfl_xor_sync(FULLM, mymax, off);
        mymax = mymax > v ? mymax : v;
    }
    if (lane == 0) wmax[warp] = mymax;
    __syncthreads();
    if (tid < 32) {
        unsigned v = (lane < 16) ? wmax[lane] : 0u;
#pragma unroll
        for (int off = 16; off; off >>= 1) {
            unsigned o = __shfl_xor_sync(FULLM, v, off);
            v = v > o ? v : o;
        }
        if (lane == 0) {
            float conf = fminf(CONF_TH, __uint_as_float(v));
            sh_confb = __float_as_uint(conf);
            sh_prefix = 0ull;
            sh_remaining = KPRE;
            ccnt = 0u;
        }
    }
    __syncthreads();
    unsigned confb = sh_confb;

    // mask invalid (score < conf) -> score field 0 (acts as -inf; index kept)
    for (int i = tid; i < NPRED; i += 512) {
        unsigned long long k = s_keys[i];
        if ((unsigned)(k >> 32) < confb) s_keys[i] = k & 0xFFFFFFFFull;
    }
    __syncthreads();

    // ---- 4x 8-bit radix passes over the score bytes (7..4) ----
    for (int p = 7; p >= 4; p--) {
        if (tid < 256) hist[tid] = 0u;
        __syncthreads();
        unsigned long long pref = sh_prefix;
        for (int it = 0; it < NITER; it++) {
            int i = it * 512 + tid;
            unsigned bucket = 0x100u;      // sentinel: inactive / non-matching
            if (i < NPRED) {
                unsigned long long k = s_keys[i];
                bool match = (p == 7) || ((k >> ((p + 1) * 8)) == pref);
                if (match) bucket = (unsigned)(k >> (p * 8)) & 0xFFu;
            }
            unsigned peers = __match_any_sync(FULLM, bucket);
            if (bucket != 0x100u && ((__ffs(peers) - 1) == lane))
                atomicAdd(&hist[bucket], __popc(peers));
        }
        __syncthreads();
        if (tid < 32) {
            int rem = sh_remaining;
            unsigned s = 0;
#pragma unroll
            for (int q = 0; q < 8; q++) s += hist[(lane << 3) + q];
            unsigned S = s;                // inclusive suffix sum across lanes
#pragma unroll
            for (int off = 1; off < 32; off <<= 1) {
                unsigned v = __shfl_down_sync(FULLM, S, off);
                if (lane + off < 32) S += v;
            }
            unsigned bal = __ballot_sync(FULLM, (int)S >= rem);
            int L = 31 - __clz(bal);       // highest lane group reaching rem
            if (lane == L) {
                int cum = (int)(S - s);    // suffix excluding this group
                for (int bb = (L << 3) + 7; bb >= (L << 3); bb--) {
                    cum += (int)hist[bb];
                    if (cum >= rem) {
                        sh_remaining = rem - (cum - (int)hist[bb]);
                        sh_prefix = (pref << 8) | (unsigned)bb;
                        break;
                    }
                }
            }
        }
        __syncthreads();
    }

    // collect keys whose score field equals the 32-bit prefix
    unsigned prefix32 = (unsigned)sh_prefix;
    for (int i = tid; i < NPRED; i += 512) {
        unsigned long long k = s_keys[i];
        if ((unsigned)(k >> 32) == prefix32) {
            unsigned pos = atomicAdd(&ccnt, 1u);
            if (pos < 256) cand[pos] = k;
        }
    }
    __syncthreads();

    if (ccnt <= 256u) {
        // direct pick: rem-th largest among candidates (keys unique)
        int rem = sh_remaining;
        if (tid < (int)ccnt) {
            unsigned long long k = cand[tid];
            int g = 0;
            for (unsigned j = 0; j < ccnt; j++) g += (cand[j] > k);
            if (g == rem - 1) sh_pivot = k;
        }
        __syncthreads();
    } else {
        // fallback: finish the remaining 4 radix passes (index bytes)
        for (int p = 3; p >= 0; p--) {
            if (tid < 256) hist[tid] = 0u;
            __syncthreads();
            unsigned long long pref = sh_prefix;
            for (int it = 0; it < NITER; it++) {
                int i = it * 512 + tid;
                unsigned bucket = 0x100u;
                if (i < NPRED) {
                    unsigned long long k = s_keys[i];
                    bool match = ((k >> ((p + 1) * 8)) == pref);
                    if (match) bucket = (unsigned)(k >> (p * 8)) & 0xFFu;
                }
                unsigned peers = __match_any_sync(FULLM, bucket);
                if (bucket != 0x100u && ((__ffs(peers) - 1) == lane))
                    atomicAdd(&hist[bucket], __popc(peers));
            }
            __syncthreads();
            if (tid < 32) {
                int rem = sh_remaining;
                unsigned s = 0;
#pragma unroll
                for (int q = 0; q < 8; q++) s += hist[(lane << 3) + q];
                unsigned S = s;
#pragma unroll
                for (int off = 1; off < 32; off <<= 1) {
                    unsigned v = __shfl_down_sync(FULLM, S, off);
                    if (lane + off < 32) S += v;
                }
                unsigned bal = __ballot_sync(FULLM, (int)S >= rem);
                int L = 31 - __clz(bal);
                if (lane == L) {
                    int cum = (int)(S - s);
                    for (int bb = (L << 3) + 7; bb >= (L << 3); bb--) {
                        cum += (int)hist[bb];
                        if (cum >= rem) {
                            sh_remaining = rem - (cum - (int)hist[bb]);
                            sh_prefix = (pref << 8) | (unsigned)bb;
                            break;
                        }
                    }
                }
            }
            __syncthreads();
        }
        if (tid == 0) sh_pivot = sh_prefix;
        __syncthreads();
    }

    unsigned long long pivot = sh_pivot;   // exact 512th-largest key
    if (tid == 0) cnt = 0u;
    __syncthreads();

    // compact: keys unique -> exactly KPRE keys >= pivot
    for (int i = tid; i < NPRED; i += 512) {
        unsigned long long k = s_keys[i];
        if (k >= pivot) {
            unsigned pos = atomicAdd(&cnt, 1u);
            topsm[pos] = k;
        }
    }
    __syncthreads();

    // bitonic sort descending (512 elems, 512 threads)
    for (int kk = 2; kk <= KPRE; kk <<= 1) {
        for (int j = kk >> 1; j > 0; j >>= 1) {
            int ixj = tid ^ j;
            if (ixj > tid) {
                bool up = ((tid & kk) == 0);
                unsigned long long a = topsm[tid], c = topsm[ixj];
                bool sw = up ? (a < c) : (a > c);
                if (sw) { topsm[tid] = c; topsm[ixj] = a; }
            }
            __syncthreads();
        }
    }
    __syncthreads();

    // ---- NMS phase: box arrays alias the dead s_keys region ----
    float* sx1 = (float*)s_keys;           // 512 each
    float* sy1 = sx1 + KPRE;
    float* sx2 = sy1 + KPRE;
    float* sy2 = sx2 + KPRE;
    float* sar = sy2 + KPRE;
    int*   sn  = (int*)(sar + KPRE);

    {
        unsigned long long key = topsm[tid];
        unsigned sb = (unsigned)(key >> 32);
        int n = (int)(~(unsigned)key);
        const float4* rec = (const float4*)(g_rows + ((size_t)b * NPRED + n) * 8);
        float4 r0 = rec[0];                  // x1,y1,x2,y2
        float4 r1 = rec[1];                  // obj,conf,cls,pad
        float off = r1.z * CLS_OFF;
        // write after barrier-protected read of s_keys is done (compact+sort
        // both behind __syncthreads above)
        sx1[tid] = r0.x + off; sy1[tid] = r0.y + off;
        sx2[tid] = r0.z + off; sy2[tid] = r0.w + off;
        sar[tid] = (r0.z - r0.x) * (r0.w - r0.y);
        sn[tid] = n;
        unsigned w = __ballot_sync(FULLM, sb != 0u);
        if (lane == 0) salive[warp] = w;
    }
    __syncthreads();

    // greedy NMS: find first alive, suppress its overlaps, repeat
    int nk = 0;
    while (nk < MAXOUT) {
        if (tid < 32) {
            unsigned a = (tid < 16) ? salive[tid] : 0u;
            unsigned bal = __ballot_sync(FULLM, a != 0u);
            int tl = bal ? (__ffs(bal) - 1) : 0;
            unsigned w = __shfl_sync(FULLM, a, tl);
            int bit = __ffs(w) - 1;
            if (tid == 0) s_i = bal ? ((tl << 5) + bit) : -1;
        }
        __syncthreads();
        int i = s_i;
        if (i < 0) break;                    // uniform
        if (tid == 0) skept[nk] = i;

        // all threads: iou(box i, box tid)
        float ix1 = fmaxf(sx1[i], sx1[tid]);
        float iy1 = fmaxf(sy1[i], sy1[tid]);
        float ix2 = fminf(sx2[i], sx2[tid]);
        float iy2 = fminf(sy2[i], sy2[tid]);
        float iw = fmaxf(ix2 - ix1, 0.f);
        float ih = fmaxf(iy2 - iy1, 0.f);
        float inter = iw * ih;
        float uni = sar[i] + sar[tid] - inter;
        float iou = inter / (uni + 1e-9f);
        unsigned bits = __ballot_sync(FULLM, iou > IOU_TH);
        if (lane == 0) {
            unsigned clr = bits | ((warp == (i >> 5)) ? (1u << (i & 31)) : 0u);
            salive[warp] &= ~clr;            // suppress overlaps + self
        }
        __syncthreads();
        nk++;
    }

    // emit: kept entries ascending -> rows [0, nk); remaining rows zeroed
    float* dets = out + (size_t)b * MAXOUT * 7;
    bool has_mask = (out_size >= BATCH * MAXOUT * 7 + BATCH * MAXOUT);
    float* mask = out + (size_t)BATCH * MAXOUT * 7 + (size_t)b * MAXOUT;

    if (tid < MAXOUT) {
        int r = tid;
        if (r < nk) {
            int i = skept[r];
            int n = sn[i];
            const float4* rec = (const float4*)(g_rows + ((size_t)b * NPRED + n) * 8);
            float4 r0 = rec[0];
            float4 r1 = rec[1];
            float* o = dets + (size_t)r * 7;
            o[0] = r0.x; o[1] = r0.y; o[2] = r0.z; o[3] = r0.w;
            o[4] = r1.x; o[5] = r1.y; o[6] = r1.z;
            if (has_mask) mask[r] = 1.0f;
        } else {
            float* o = dets + (size_t)r * 7;
#pragma unroll
            for (int c = 0; c < 7; c++) o[c] = 0.f;
            if (has_mask) mask[r] = 0.f;
        }
    }
}

// ---------------------------------------------------------------------------
extern "C" void kernel_launch(void* const* d_in, const int* in_sizes, int n_in,
                              void* d_out, int out_size) {
    (void)in_sizes; (void)n_in;
    const float* pred = (const float*)d_in[0];
    float* out = (float*)d_out;

    static_assert(NPRED % RPB == 0, "rows per block");
    static_assert((RPB * ROWF) % 4 == 0, "float4 staging");
    static_assert((NPRED * ROWF) % 4 == 0, "float4 batch base");
    static_assert(6 * KPRE * 4 <= NPRED * 8, "nms smem alias fits");

    cudaFuncSetAttribute(k_selnms, cudaFuncAttributeMaxDynamicSharedMemorySize,
                         (NPRED + KPRE) * 8);

    dim3 gs(NPRED / RPB, BATCH);           // (70, 32)
    k_score<<<gs, 128>>>(pred);
    k_selnms<<<BATCH, 512, (NPRED + KPRE) * 8>>>(out, out_size);
}

// round 14
// speedup vs baseline: 1.4051x; 1.4051x over previous
#include <cuda_runtime.h>
#include <cstdint>

#define BATCH   32
#define NPRED   8400
#define NCLS    80
#define ROWF    85
#define KPRE    512
#define MAXOUT  100
#define RPB     120         // rows per k_score block: 120*85*4 = 40800 B smem
#define CONF_TH 0.25f
#define IOU_TH  0.45f
#define CLS_OFF 4096.0f
#define FULLM   0xFFFFFFFFu

// Scratch (no allocations allowed -> device globals)
__device__ unsigned long long g_keys[BATCH * NPRED];
__device__ unsigned long long g_topk[BATCH * KPRE];
__device__ float              g_box[5 * BATCH * KPRE];   // SoA: x1,y1,x2,y2,area (class-offset applied)
__device__ float              g_det[BATCH * KPRE * 7];   // x1,y1,x2,y2,obj,conf,cls
__device__ unsigned char      g_validb[BATCH * KPRE];

// ---------------------------------------------------------------------------
// K1: streaming score pass. Block stages 120 rows into smem with coalesced
// LDG.128, then thread-per-row PURE MAX via 4 independent FMNMX chains
// (no argmax here -> no predicated-move dependency chain; argmax is
// recomputed in k_gather for only the 512 selected rows per batch).
// key = (score_bits<<32) | ~n  (unique).
// ---------------------------------------------------------------------------
__global__ void __launch_bounds__(128) k_score(const float* __restrict__ pred) {
    __shared__ float srow[RPB * ROWF];     // 40800 B
    int tid = threadIdx.x;                 // 128
    int b = blockIdx.y;
    int row0 = blockIdx.x * RPB;

    // base element index multiple of 4: RPB*ROWF = 10200, NPRED*ROWF = 714000
    const float4* src = (const float4*)(pred + ((size_t)b * NPRED + row0) * ROWF);
    float4* dst4 = (float4*)srow;
#pragma unroll
    for (int i = 0; i < RPB * ROWF / 4 / 128 + 1; i++) {
        int idx = i * 128 + tid;
        if (idx < RPB * ROWF / 4) dst4[idx] = src[idx];
    }
    __syncthreads();

    if (tid < RPB) {
        const float* row = srow + tid * ROWF;   // stride 85 words: conflict-free
        // 4 independent running-max chains over the 80 class scores
        float m0 = row[5], m1 = row[6], m2 = row[7], m3 = row[8];
#pragma unroll
        for (int c = 9; c < 5 + NCLS; c += 4) {
            m0 = fmaxf(m0, row[c]);
            m1 = fmaxf(m1, row[c + 1]);
            m2 = fmaxf(m2, row[c + 2]);
            m3 = fmaxf(m3, row[c + 3]);
        }
        float bv = fmaxf(fmaxf(m0, m1), fmaxf(m2, m3));
        float score = row[4] * bv;                // >= 0
        unsigned sb = __float_as_uint(score);     // positive-float bit order == int order
        int n = row0 + tid;
        g_keys[(size_t)b * NPRED + n] =
            ((unsigned long long)sb << 32) | (unsigned)(~(unsigned)n);
    }
}

// ---------------------------------------------------------------------------
// K2: per-batch conf (= min(0.25, max score)) + exact top-512 radix-select on
// unique 64-bit keys + bitonic sort descending. One 512-thread block / batch.
// (Reverted to the measured-good 8-pass version.)
// ---------------------------------------------------------------------------
__global__ void k_select() {
    extern __shared__ unsigned long long s_keys[];   // NPRED + KPRE entries
    unsigned long long* topsm = s_keys + NPRED;

    __shared__ unsigned int        hist[256];
    __shared__ unsigned int        wmax[16];
    __shared__ unsigned int        sh_confb;
    __shared__ unsigned long long  sh_prefix;
    __shared__ int                 sh_remaining;
    __shared__ unsigned int        cnt;

    int b = blockIdx.x;
    int tid = threadIdx.x;                 // 512
    int warp = tid >> 5, lane = tid & 31;  // 16 warps
    const int NITER = (NPRED + 511) / 512; // uniform trip count (17)

    // load keys + running max of score field
    unsigned mymax = 0u;
    for (int i = tid; i < NPRED; i += 512) {
        unsigned long long k = g_keys[(size_t)b * NPRED + i];
        s_keys[i] = k;
        unsigned sb = (unsigned)(k >> 32);
        mymax = mymax > sb ? mymax : sb;
    }
#pragma unroll
    for (int off = 16; off; off >>= 1) {
        unsigned v = __shfl_xor_sync(FULLM, mymax, off);
        mymax = mymax > v ? mymax : v;
    }
    if (lane == 0) wmax[warp] = mymax;
    __syncthreads();
    if (tid < 32) {
        unsigned v = (lane < 16) ? wmax[lane] : 0u;
#pragma unroll
        for (int off = 16; off; off >>= 1) {
            unsigned o = __shfl_xor_sync(FULLM, v, off);
            v = v > o ? v : o;
        }
        if (lane == 0) {
            float conf = fminf(CONF_TH, __uint_as_float(v));
            sh_confb = __float_as_uint(conf);
            sh_prefix = 0ull;
            sh_remaining = KPRE;
        }
    }
    __syncthreads();
    unsigned confb = sh_confb;

    // mask invalid (score < conf) -> score field 0 (acts as -inf; index kept)
    for (int i = tid; i < NPRED; i += 512) {
        unsigned long long k = s_keys[i];
        if ((unsigned)(k >> 32) < confb) s_keys[i] = k & 0xFFFFFFFFull;
    }
    __syncthreads();

    // 8x 8-bit radix select: find exact KPRE-th largest key
    for (int p = 7; p >= 0; p--) {
        if (tid < 256) hist[tid] = 0u;
        __syncthreads();
        unsigned long long pref = sh_prefix;
        // uniform trip count: every lane executes __match_any every iteration
        for (int it = 0; it < NITER; it++) {
            int i = it * 512 + tid;
            unsigned bucket = 0x100u;      // sentinel: inactive / non-matching
            if (i < NPRED) {
                unsigned long long k = s_keys[i];
                bool match = (p == 7) || ((k >> ((p + 1) * 8)) == pref);
                if (match) bucket = (unsigned)(k >> (p * 8)) & 0xFFu;
            }
            unsigned peers = __match_any_sync(FULLM, bucket);
            if (bucket != 0x100u && ((__ffs(peers) - 1) == lane))
                atomicAdd(&hist[bucket], __popc(peers));
        }
        __syncthreads();
        if (tid < 32) {
            int rem = sh_remaining;
            unsigned s = 0;
#pragma unroll
            for (int q = 0; q < 8; q++) s += hist[(lane << 3) + q];
            unsigned S = s;                // inclusive suffix sum across lanes
#pragma unroll
            for (int off = 1; off < 32; off <<= 1) {
                unsigned v = __shfl_down_sync(FULLM, S, off);
                if (lane + off < 32) S += v;
            }
            unsigned bal = __ballot_sync(FULLM, (int)S >= rem);
            int L = 31 - __clz(bal);       // highest lane group reaching rem
            if (lane == L) {
                int cum = (int)(S - s);    // suffix excluding this group
                for (int bb = (L << 3) + 7; bb >= (L << 3); bb--) {
                    cum += (int)hist[bb];
                    if (cum >= rem) {
                        sh_remaining = rem - (cum - (int)hist[bb]);
                        sh_prefix = (pref << 8) | (unsigned)bb;
                        break;
                    }
                }
            }
        }
        __syncthreads();
    }

    unsigned long long pivot = sh_prefix;   // exact 512th-largest key
    if (tid == 0) cnt = 0u;
    __syncthreads();

    // compact: keys unique -> exactly KPRE keys >= pivot
    for (int i = tid; i < NPRED; i += 512) {
        unsigned long long k = s_keys[i];
        if (k >= pivot) {
            unsigned pos = atomicAdd(&cnt, 1u);
            topsm[pos] = k;
        }
    }
    __syncthreads();

    // bitonic sort descending (512 elems, 512 threads)
    for (int kk = 2; kk <= KPRE; kk <<= 1) {
        for (int j = kk >> 1; j > 0; j >>= 1) {
            int ixj = tid ^ j;
            if (ixj > tid) {
                bool up = ((tid & kk) == 0);
                unsigned long long a = topsm[tid], c = topsm[ixj];
                bool sw = up ? (a < c) : (a > c);
                if (sw) { topsm[tid] = c; topsm[ixj] = a; }
            }
            __syncthreads();
        }
    }

    for (int i = tid; i < KPRE; i += 512)
        g_topk[(size_t)b * KPRE + i] = topsm[i];
}

// ---------------------------------------------------------------------------
// K3: gather selected rows -> boxes (class-offset) + dets + valid bytes.
// Grid (64, BATCH) x 256 threads, one warp per entry: latency fully hidden.
// Argmax over 80 classes done here (only 512 rows per batch).
// ---------------------------------------------------------------------------
__global__ void k_gather(const float* __restrict__ pred) {
    int warp = threadIdx.x >> 5, lane = threadIdx.x & 31;
    int b = blockIdx.y;
    int e = blockIdx.x * 8 + warp;

    unsigned long long key = g_topk[(size_t)b * KPRE + e];
    unsigned sb = (unsigned)(key >> 32);
    int n = (int)(~(unsigned)key);
    const float* row = pred + ((size_t)b * NPRED + n) * ROWF;

    float bv = -1.f; int bi = 0;
#pragma unroll
    for (int i = 0; i < 3; i++) {
        int c = lane + i * 32;
        if (c < NCLS) {
            float v = row[5 + c];
            if (v > bv) { bv = v; bi = c; }
        }
    }
#pragma unroll
    for (int off = 16; off; off >>= 1) {
        float ov = __shfl_xor_sync(FULLM, bv, off);
        int   oi = __shfl_xor_sync(FULLM, bi, off);
        if (ov > bv || (ov == bv && oi < bi)) { bv = ov; bi = oi; }
    }
    if (lane == 0) {
        float cx = row[0], cy = row[1], w = row[2], h = row[3], obj = row[4];
        float x1 = cx - 0.5f * w, y1 = cy - 0.5f * h;
        float x2 = cx + 0.5f * w, y2 = cy + 0.5f * h;
        float off = (float)bi * CLS_OFF;
        int base = b * KPRE + e;
        g_box[0 * BATCH * KPRE + base] = x1 + off;
        g_box[1 * BATCH * KPRE + base] = y1 + off;
        g_box[2 * BATCH * KPRE + base] = x2 + off;
        g_box[3 * BATCH * KPRE + base] = y2 + off;
        g_box[4 * BATCH * KPRE + base] = (x2 - x1) * (y2 - y1);
        float* d = g_det + (size_t)base * 7;
        d[0] = x1; d[1] = y1; d[2] = x2; d[3] = y2;
        d[4] = obj; d[5] = bv; d[6] = (float)bi;
        g_validb[base] = (sb != 0u) ? 1 : 0;   // unconditional -> no init kernel
    }
}

// ---------------------------------------------------------------------------
// K4: on-demand-IoU greedy NMS + emit. One 256-thread block per batch.
// IoU computed only against kept boxes (~100 of 512): each iteration all 256
// threads compute 2 IoUs; per-warp ballots clear the alive mask. Early exit
// at 100 kept. Replaces the full 512x512 IoU matrix.
// ---------------------------------------------------------------------------
__global__ void k_nms(float* __restrict__ out, int out_size) {
    __shared__ float sx1[KPRE], sy1[KPRE], sx2[KPRE], sy2[KPRE], sar[KPRE];
    __shared__ unsigned salive[16];
    __shared__ int skept[MAXOUT];
    __shared__ int s_i;

    int b = blockIdx.x, tid = threadIdx.x;   // 256
    int warp = tid >> 5, lane = tid & 31;    // 8 warps

    // load boxes SoA (coalesced) + build alive mask from valid bytes
#pragma unroll
    for (int r = 0; r < 2; r++) {
        int idx = r * 256 + tid;
        int base = b * KPRE + idx;
        sx1[idx] = g_box[0 * BATCH * KPRE + base];
        sy1[idx] = g_box[1 * BATCH * KPRE + base];
        sx2[idx] = g_box[2 * BATCH * KPRE + base];
        sy2[idx] = g_box[3 * BATCH * KPRE + base];
        sar[idx] = g_box[4 * BATCH * KPRE + base];
        bool v = g_validb[base] != 0;
        unsigned w = __ballot_sync(FULLM, v);
        if (lane == 0) salive[idx >> 5] = w;
    }
    __syncthreads();

    // greedy NMS: find first alive, suppress its overlaps, repeat
    int nk = 0;
    while (nk < MAXOUT) {
        if (tid < 32) {
            unsigned a = (tid < 16) ? salive[tid] : 0u;
            unsigned bal = __ballot_sync(FULLM, a != 0u);
            int tl = bal ? (__ffs(bal) - 1) : 0;
            unsigned w = __shfl_sync(FULLM, a, tl);
            int bit = __ffs(w) - 1;
            if (tid == 0) s_i = bal ? ((tl << 5) + bit) : -1;
        }
        __syncthreads();
        int i = s_i;
        if (i < 0) break;                    // uniform
        if (tid == 0) skept[nk] = i;

        float bx1 = sx1[i], by1 = sy1[i], bx2 = sx2[i], by2 = sy2[i], ba = sar[i];

        // j0 = tid, j1 = tid + 256
        int j0 = tid, j1 = tid + 256;
        float iw0 = fmaxf(fminf(bx2, sx2[j0]) - fmaxf(bx1, sx1[j0]), 0.f);
        float ih0 = fmaxf(fminf(by2, sy2[j0]) - fmaxf(by1, sy1[j0]), 0.f);
        float in0 = iw0 * ih0;
        float io0 = in0 / (ba + sar[j0] - in0 + 1e-9f);
        float iw1 = fmaxf(fminf(bx2, sx2[j1]) - fmaxf(bx1, sx1[j1]), 0.f);
        float ih1 = fmaxf(fminf(by2, sy2[j1]) - fmaxf(by1, sy1[j1]), 0.f);
        float in1 = iw1 * ih1;
        float io1 = in1 / (ba + sar[j1] - in1 + 1e-9f);

        unsigned bits0 = __ballot_sync(FULLM, io0 > IOU_TH);   // word warp
        unsigned bits1 = __ballot_sync(FULLM, io1 > IOU_TH);   // word warp+8
        if (lane == 0) {
            unsigned c0 = bits0, c1 = bits1;
            int iw = i >> 5;
            if (iw == warp)     c0 |= 1u << (i & 31);          // self bit
            if (iw == warp + 8) c1 |= 1u << (i & 31);
            salive[warp]     &= ~c0;
            salive[warp + 8] &= ~c1;
        }
        __syncthreads();
        nk++;
    }

    // emit: kept entries ascending -> rows [0, nk); remaining rows zeroed
    float* dets = out + (size_t)b * MAXOUT * 7;
    bool has_mask = (out_size >= BATCH * MAXOUT * 7 + BATCH * MAXOUT);
    float* mask = out + (size_t)BATCH * MAXOUT * 7 + (size_t)b * MAXOUT;

    if (tid < MAXOUT) {
        int r = tid;
        if (r < nk) {
            int i = skept[r];
            const float* d = g_det + ((size_t)b * KPRE + i) * 7;
            float* o = dets + (size_t)r * 7;
#pragma unroll
            for (int c = 0; c < 7; c++) o[c] = d[c];
            if (has_mask) mask[r] = 1.0f;
        } else {
            float* o = dets + (size_t)r * 7;
#pragma unroll
            for (int c = 0; c < 7; c++) o[c] = 0.f;
            if (has_mask) mask[r] = 0.f;
        }
    }
}

// ---------------------------------------------------------------------------
extern "C" void kernel_launch(void* const* d_in, const int* in_sizes, int n_in,
                              void* d_out, int out_size) {
    (void)in_sizes; (void)n_in;
    const float* pred = (const float*)d_in[0];
    float* out = (float*)d_out;

    static_assert(NPRED % RPB == 0, "rows per block");
    static_assert((RPB * ROWF) % 4 == 0, "float4 staging");
    static_assert((NPRED * ROWF) % 4 == 0, "float4 batch base");
    static_assert((NCLS - 4) % 4 == 0, "4-way max chains cover classes");

    cudaFuncSetAttribute(k_select, cudaFuncAttributeMaxDynamicSharedMemorySize,
                         (NPRED + KPRE) * 8);

    dim3 gs(NPRED / RPB, BATCH);           // (70, 32)
    k_score<<<gs, 128>>>(pred);
    k_select<<<BATCH, 512, (NPRED + KPRE) * 8>>>();
    dim3 gg(KPRE / 8, BATCH);              // (64, 32)
    k_gather<<<gg, 256>>>(pred);
    k_nms<<<BATCH, 256>>>(out, out_size);
}

// round 15
// speedup vs baseline: 1.8100x; 1.2881x over previous
#include <cuda_runtime.h>
#include <cstdint>

#define BATCH   32
#define NPRED   8400
#define NCLS    80
#define ROWF    85
#define KPRE    512
#define MAXOUT  100
#define RPB     120         // rows per k_score block: 120*85*4 = 40800 B smem
#define CONF_TH 0.25f
#define IOU_TH  0.45f
#define CLS_OFF 4096.0f
#define FULLM   0xFFFFFFFFu

// Scratch (no allocations allowed -> device globals)
__device__ unsigned long long g_keys[BATCH * NPRED];
__device__ unsigned long long g_topk[BATCH * KPRE];
__device__ float              g_box[5 * BATCH * KPRE];   // SoA: x1,y1,x2,y2,area (class-offset applied)
__device__ float              g_det[BATCH * KPRE * 7];   // x1,y1,x2,y2,obj,conf,cls
__device__ unsigned char      g_validb[BATCH * KPRE];
__device__ unsigned int       g_sup[BATCH * KPRE * 16];  // 1 MB suppression bitmask (upper-tri valid)

// ---------------------------------------------------------------------------
// K1: streaming score pass. Block stages 120 rows into smem with coalesced
// LDG.128, then thread-per-row PURE MAX via 4 independent FMNMX chains
// (argmax deferred to k_gather, which touches only 512 rows per batch).
// key = (score_bits<<32) | ~n  (unique).
// ---------------------------------------------------------------------------
__global__ void __launch_bounds__(128) k_score(const float* __restrict__ pred) {
    __shared__ float srow[RPB * ROWF];     // 40800 B
    int tid = threadIdx.x;                 // 128
    int b = blockIdx.y;
    int row0 = blockIdx.x * RPB;

    // base element index multiple of 4: RPB*ROWF = 10200, NPRED*ROWF = 714000
    const float4* src = (const float4*)(pred + ((size_t)b * NPRED + row0) * ROWF);
    float4* dst4 = (float4*)srow;
#pragma unroll
    for (int i = 0; i < RPB * ROWF / 4 / 128 + 1; i++) {
        int idx = i * 128 + tid;
        if (idx < RPB * ROWF / 4) dst4[idx] = src[idx];
    }
    __syncthreads();

    if (tid < RPB) {
        const float* row = srow + tid * ROWF;   // stride 85 words: conflict-free
        // 4 independent running-max chains over the 80 class scores
        float m0 = row[5], m1 = row[6], m2 = row[7], m3 = row[8];
#pragma unroll
        for (int c = 9; c < 5 + NCLS; c += 4) {
            m0 = fmaxf(m0, row[c]);
            m1 = fmaxf(m1, row[c + 1]);
            m2 = fmaxf(m2, row[c + 2]);
            m3 = fmaxf(m3, row[c + 3]);
        }
        float bv = fmaxf(fmaxf(m0, m1), fmaxf(m2, m3));
        float score = row[4] * bv;                // >= 0
        unsigned sb = __float_as_uint(score);     // positive-float bit order == int order
        int n = row0 + tid;
        g_keys[(size_t)b * NPRED + n] =
            ((unsigned long long)sb << 32) | (unsigned)(~(unsigned)n);
    }
}

// ---------------------------------------------------------------------------
// K2: per-batch conf (= min(0.25, max score)) + exact top-512 radix-select on
// unique 64-bit keys + bitonic sort descending. One 512-thread block / batch.
// ---------------------------------------------------------------------------
__global__ void k_select() {
    extern __shared__ unsigned long long s_keys[];   // NPRED + KPRE entries
    unsigned long long* topsm = s_keys + NPRED;

    __shared__ unsigned int        hist[256];
    __shared__ unsigned int        wmax[16];
    __shared__ unsigned int        sh_confb;
    __shared__ unsigned long long  sh_prefix;
    __shared__ int                 sh_remaining;
    __shared__ unsigned int        cnt;

    int b = blockIdx.x;
    int tid = threadIdx.x;                 // 512
    int warp = tid >> 5, lane = tid & 31;  // 16 warps
    const int NITER = (NPRED + 511) / 512; // uniform trip count (17)

    // load keys + running max of score field
    unsigned mymax = 0u;
    for (int i = tid; i < NPRED; i += 512) {
        unsigned long long k = g_keys[(size_t)b * NPRED + i];
        s_keys[i] = k;
        unsigned sb = (unsigned)(k >> 32);
        mymax = mymax > sb ? mymax : sb;
    }
#pragma unroll
    for (int off = 16; off; off >>= 1) {
        unsigned v = __shfl_xor_sync(FULLM, mymax, off);
        mymax = mymax > v ? mymax : v;
    }
    if (lane == 0) wmax[warp] = mymax;
    __syncthreads();
    if (tid < 32) {
        unsigned v = (lane < 16) ? wmax[lane] : 0u;
#pragma unroll
        for (int off = 16; off; off >>= 1) {
            unsigned o = __shfl_xor_sync(FULLM, v, off);
            v = v > o ? v : o;
        }
        if (lane == 0) {
            float conf = fminf(CONF_TH, __uint_as_float(v));
            sh_confb = __float_as_uint(conf);
            sh_prefix = 0ull;
            sh_remaining = KPRE;
        }
    }
    __syncthreads();
    unsigned confb = sh_confb;

    // mask invalid (score < conf) -> score field 0 (acts as -inf; index kept)
    for (int i = tid; i < NPRED; i += 512) {
        unsigned long long k = s_keys[i];
        if ((unsigned)(k >> 32) < confb) s_keys[i] = k & 0xFFFFFFFFull;
    }
    __syncthreads();

    // 8x 8-bit radix select: find exact KPRE-th largest key
    for (int p = 7; p >= 0; p--) {
        if (tid < 256) hist[tid] = 0u;
        __syncthreads();
        unsigned long long pref = sh_prefix;
        // uniform trip count: every lane executes __match_any every iteration
        for (int it = 0; it < NITER; it++) {
            int i = it * 512 + tid;
            unsigned bucket = 0x100u;      // sentinel: inactive / non-matching
            if (i < NPRED) {
                unsigned long long k = s_keys[i];
                bool match = (p == 7) || ((k >> ((p + 1) * 8)) == pref);
                if (match) bucket = (unsigned)(k >> (p * 8)) & 0xFFu;
            }
            unsigned peers = __match_any_sync(FULLM, bucket);
            if (bucket != 0x100u && ((__ffs(peers) - 1) == lane))
                atomicAdd(&hist[bucket], __popc(peers));
        }
        __syncthreads();
        if (tid < 32) {
            int rem = sh_remaining;
            unsigned s = 0;
#pragma unroll
            for (int q = 0; q < 8; q++) s += hist[(lane << 3) + q];
            unsigned S = s;                // inclusive suffix sum across lanes
#pragma unroll
            for (int off = 1; off < 32; off <<= 1) {
                unsigned v = __shfl_down_sync(FULLM, S, off);
                if (lane + off < 32) S += v;
            }
            unsigned bal = __ballot_sync(FULLM, (int)S >= rem);
            int L = 31 - __clz(bal);       // highest lane group reaching rem
            if (lane == L) {
                int cum = (int)(S - s);    // suffix excluding this group
                for (int bb = (L << 3) + 7; bb >= (L << 3); bb--) {
                    cum += (int)hist[bb];
                    if (cum >= rem) {
                        sh_remaining = rem - (cum - (int)hist[bb]);
                        sh_prefix = (pref << 8) | (unsigned)bb;
                        break;
                    }
                }
            }
        }
        __syncthreads();
    }

    unsigned long long pivot = sh_prefix;   // exact 512th-largest key
    if (tid == 0) cnt = 0u;
    __syncthreads();

    // compact: keys unique -> exactly KPRE keys >= pivot
    for (int i = tid; i < NPRED; i += 512) {
        unsigned long long k = s_keys[i];
        if (k >= pivot) {
            unsigned pos = atomicAdd(&cnt, 1u);
            topsm[pos] = k;
        }
    }
    __syncthreads();

    // bitonic sort descending (512 elems, 512 threads)
    for (int kk = 2; kk <= KPRE; kk <<= 1) {
        for (int j = kk >> 1; j > 0; j >>= 1) {
            int ixj = tid ^ j;
            if (ixj > tid) {
                bool up = ((tid & kk) == 0);
                unsigned long long a = topsm[tid], c = topsm[ixj];
                bool sw = up ? (a < c) : (a > c);
                if (sw) { topsm[tid] = c; topsm[ixj] = a; }
            }
            __syncthreads();
        }
    }

    for (int i = tid; i < KPRE; i += 512)
        g_topk[(size_t)b * KPRE + i] = topsm[i];
}

// ---------------------------------------------------------------------------
// K3: gather selected rows -> boxes (class-offset) + dets + valid bytes.
// Grid (64, BATCH) x 256 threads, one warp per entry: latency fully hidden.
// Argmax over 80 classes done here (only 512 rows per batch).
// ---------------------------------------------------------------------------
__global__ void k_gather(const float* __restrict__ pred) {
    int warp = threadIdx.x >> 5, lane = threadIdx.x & 31;
    int b = blockIdx.y;
    int e = blockIdx.x * 8 + warp;

    unsigned long long key = g_topk[(size_t)b * KPRE + e];
    unsigned sb = (unsigned)(key >> 32);
    int n = (int)(~(unsigned)key);
    const float* row = pred + ((size_t)b * NPRED + n) * ROWF;

    float bv = -1.f; int bi = 0;
#pragma unroll
    for (int i = 0; i < 3; i++) {
        int c = lane + i * 32;
        if (c < NCLS) {
            float v = row[5 + c];
            if (v > bv) { bv = v; bi = c; }
        }
    }
#pragma unroll
    for (int off = 16; off; off >>= 1) {
        float ov = __shfl_xor_sync(FULLM, bv, off);
        int   oi = __shfl_xor_sync(FULLM, bi, off);
        if (ov > bv || (ov == bv && oi < bi)) { bv = ov; bi = oi; }
    }
    if (lane == 0) {
        float cx = row[0], cy = row[1], w = row[2], h = row[3], obj = row[4];
        float x1 = cx - 0.5f * w, y1 = cy - 0.5f * h;
        float x2 = cx + 0.5f * w, y2 = cy + 0.5f * h;
        float off = (float)bi * CLS_OFF;
        int base = b * KPRE + e;
        g_box[0 * BATCH * KPRE + base] = x1 + off;
        g_box[1 * BATCH * KPRE + base] = y1 + off;
        g_box[2 * BATCH * KPRE + base] = x2 + off;
        g_box[3 * BATCH * KPRE + base] = y2 + off;
        g_box[4 * BATCH * KPRE + base] = (x2 - x1) * (y2 - y1);
        float* d = g_det + (size_t)base * 7;
        d[0] = x1; d[1] = y1; d[2] = x2; d[3] = y2;
        d[4] = obj; d[5] = bv; d[6] = (float)bi;
        g_validb[base] = (sb != 0u) ? 1 : 0;   // unconditional -> no init kernel
    }
}

// ---------------------------------------------------------------------------
// K4: suppression bitmask, UPPER TRIANGLE ONLY: row i gets words wd >= i>>5.
// (Greedy NMS processes kept boxes in increasing index; when i is kept, all
// alive bits j<i are already 0, so lower-triangle words are never consumed.)
// Grid (32, BATCH) x 512 threads: one warp per row i, ballot forms each word.
// ---------------------------------------------------------------------------
__global__ void k_iou() {
    __shared__ float sx1[KPRE], sy1[KPRE], sx2[KPRE], sy2[KPRE], sar[KPRE];
    int b = blockIdx.y;
    int tid = threadIdx.x;                 // 512
    int warp = tid >> 5, lane = tid & 31;  // 16 warps

    {
        int base = b * KPRE + tid;
        sx1[tid] = g_box[0 * BATCH * KPRE + base];
        sy1[tid] = g_box[1 * BATCH * KPRE + base];
        sx2[tid] = g_box[2 * BATCH * KPRE + base];
        sy2[tid] = g_box[3 * BATCH * KPRE + base];
        sar[tid] = g_box[4 * BATCH * KPRE + base];
    }
    __syncthreads();

    int i = blockIdx.x * 16 + warp;        // this warp's row
    float ax1 = sx1[i], ay1 = sy1[i], ax2 = sx2[i], ay2 = sy2[i], aa = sar[i];
    unsigned* dst = g_sup + ((size_t)b * KPRE + i) * 16;

    for (int wd = (i >> 5); wd < 16; wd++) {
        int j = (wd << 5) + lane;
        float ix1 = fmaxf(ax1, sx1[j]);
        float iy1 = fmaxf(ay1, sy1[j]);
        float ix2 = fminf(ax2, sx2[j]);
        float iy2 = fminf(ay2, sy2[j]);
        float iw = fmaxf(ix2 - ix1, 0.f);
        float ih = fmaxf(iy2 - iy1, 0.f);
        float inter = iw * ih;
        float uni = aa + sar[j] - inter;
        float iou = inter / (uni + 1e-9f);
        unsigned bits = __ballot_sync(FULLM, iou > IOU_TH);
        if (lane == 0) dst[wd] = bits;
    }
}

// ---------------------------------------------------------------------------
// K5: kept-box-centric greedy NMS (single warp, register-resident alive mask,
// early exit at 100 kept) + emit. One block (256 threads) per batch.
// ---------------------------------------------------------------------------
__global__ void k_nms(float* __restrict__ out, int out_size) {
    __shared__ unsigned ssup[KPRE * 16];   // 32 KB
    __shared__ unsigned svalid[16];
    __shared__ int skept[MAXOUT];
    __shared__ int snk;

    int b = blockIdx.x, tid = threadIdx.x;   // 256

    // stage suppression mask (L2-resident) into smem, vectorized
    {
        const uint4* src = (const uint4*)(g_sup + (size_t)b * KPRE * 16);
        uint4* dstv = (uint4*)ssup;
        for (int i = tid; i < KPRE * 16 / 4; i += 256) dstv[i] = src[i];
    }
    // build valid bitmask from bytes (uniform full-warp ballots)
#pragma unroll
    for (int r = 0; r < 2; r++) {
        int idx = r * 256 + tid;
        bool v = g_validb[b * KPRE + idx] != 0;
        unsigned w = __ballot_sync(FULLM, v);
        if ((tid & 31) == 0) svalid[idx >> 5] = w;
    }
    __syncthreads();

    if (tid < 32) {
        int lane = tid;
        unsigned alive = (lane < 16) ? svalid[lane] : 0u;
        int nk = 0;
        while (nk < MAXOUT) {
            unsigned bal = __ballot_sync(FULLM, alive != 0u);
            if (!bal) break;
            int tl = __ffs(bal) - 1;                       // first lane with alive bits
            unsigned w = __shfl_sync(FULLM, alive, tl);
            int bit = __ffs(w) - 1;
            int i = (tl << 5) + bit;                       // first alive index = next kept
            if (lane == 0) skept[nk] = i;
            nk++;
            unsigned sup = (lane < 16) ? ssup[i * 16 + lane] : 0u;
            alive &= ~sup;                                 // suppress overlapping later boxes
            if (lane == tl) alive &= ~(1u << bit);         // self
        }
        if (lane == 0) snk = nk;
    }
    __syncthreads();

    int nk = snk;
    float* dets = out + (size_t)b * MAXOUT * 7;
    bool has_mask = (out_size >= BATCH * MAXOUT * 7 + BATCH * MAXOUT);
    float* mask = out + (size_t)BATCH * MAXOUT * 7 + (size_t)b * MAXOUT;

    if (tid < MAXOUT) {
        int r = tid;
        if (r < nk) {
            int i = skept[r];
            const float* d = g_det + ((size_t)b * KPRE + i) * 7;
            float* o = dets + (size_t)r * 7;
#pragma unroll
            for (int c = 0; c < 7; c++) o[c] = d[c];
            if (has_mask) mask[r] = 1.0f;
        } else {
            float* o = dets + (size_t)r * 7;
#pragma unroll
            for (int c = 0; c < 7; c++) o[c] = 0.f;
            if (has_mask) mask[r] = 0.f;
        }
    }
}

// ---------------------------------------------------------------------------
extern "C" void kernel_launch(void* const* d_in, const int* in_sizes, int n_in,
                              void* d_out, int out_size) {
    (void)in_sizes; (void)n_in;
    const float* pred = (const float*)d_in[0];
    float* out = (float*)d_out;

    static_assert(NPRED % RPB == 0, "rows per block");
    static_assert((RPB * ROWF) % 4 == 0, "float4 staging");
    static_assert((NPRED * ROWF) % 4 == 0, "float4 batch base");
    static_assert((NCLS - 4) % 4 == 0, "4-way max chains cover classes");

    cudaFuncSetAttribute(k_select, cudaFuncAttributeMaxDynamicSharedMemorySize,
                         (NPRED + KPRE) * 8);

    dim3 gs(NPRED / RPB, BATCH);           // (70, 32)
    k_score<<<gs, 128>>>(pred);
    k_select<<<BATCH, 512, (NPRED + KPRE) * 8>>>();
    dim3 gg(KPRE / 8, BATCH);              // (64, 32)
    k_gather<<<gg, 256>>>(pred);
    dim3 gi(KPRE / 16, BATCH);             // (32, 32)
    k_iou<<<gi, 512>>>();
    k_nms<<<BATCH, 256>>>(out, out_size);
}